// round 2
// baseline (speedup 1.0000x reference)
#include <cuda_runtime.h>
#include <cstdint>

#define KOUT     512
#define NTHREADS 512
#define NBINS    4096
#define BPT      (NBINS / NTHREADS)   // bins per thread = 8
#define BUFCAP   2048

// monotone bijection float -> uint32 (ascending order preserved)
__device__ __forceinline__ unsigned fkey(float f) {
    unsigned u = __float_as_uint(f);
    return u ^ ((u & 0x80000000u) ? 0xFFFFFFFFu : 0x80000000u);
}
__device__ __forceinline__ float finv(unsigned v) {
    unsigned u = v ^ ((v & 0x80000000u) ? 0x80000000u : 0xFFFFFFFFu);
    return __uint_as_float(u);
}

// Block-wide: find smallest bin p such that cumsum(hist[0..p]) >= target.
// Writes *s_pivot and *s_below (count strictly below bin p). All threads call.
__device__ __forceinline__ void find_pivot(int* hist, int target,
                                           int* s_pivot, int* s_below,
                                           int* wsum) {
    const int t = threadIdx.x;
    const int base = t * BPT;
    int local = 0;
#pragma unroll
    for (int j = 0; j < BPT; j++) local += hist[base + j];

    const int lane = t & 31, warp = t >> 5;
    int incl = local;
#pragma unroll
    for (int o = 1; o < 32; o <<= 1) {
        int v = __shfl_up_sync(0xFFFFFFFFu, incl, o);
        if (lane >= o) incl += v;
    }
    if (lane == 31) wsum[warp] = incl;
    __syncthreads();
    if (t == 0) {
        int acc = 0;
#pragma unroll
        for (int i = 0; i < NTHREADS / 32; i++) { int v = wsum[i]; wsum[i] = acc; acc += v; }
    }
    __syncthreads();
    const int excl = wsum[warp] + incl - local;
    if (excl < target && excl + local >= target) {
        int c = excl;
#pragma unroll
        for (int j = 0; j < BPT; j++) {
            int h = hist[base + j];
            if (c + h >= target) { *s_pivot = base + j; *s_below = c; break; }
            c += h;
        }
    }
    __syncthreads();
}

__global__ __launch_bounds__(NTHREADS)
void topk_sort_kernel(const float2* __restrict__ corners,
                      const int*    __restrict__ lengths,
                      float2*       __restrict__ out,
                      int M) {
    __shared__ int hist[NBINS];
    __shared__ unsigned long long buf[BUFCAP];
    __shared__ int wsum[NTHREADS / 32];
    __shared__ int s_pivot, s_below, s_cnt;

    const int b = blockIdx.x;
    const int t = threadIdx.x;
    const int n  = lengths[b];
    const int kk = n < KOUT ? n : KOUT;
    float2* outp = out + (size_t)b * KOUT;

    if (kk == 0) {                // entire row is padding
        outp[t] = make_float2(0.f, 0.f);
        return;
    }

    const float2* base = corners + (size_t)b * M;

    // ---- Pass 1: histogram of top 12 bits of sortable(x) ----
    for (int i = t; i < NBINS; i += NTHREADS) hist[i] = 0;
    __syncthreads();
    for (int i = t; i < n; i += NTHREADS) {
        float2 c = __ldg(base + i);
        unsigned u = fkey(c.x);
        atomicAdd(&hist[u >> 20], 1);
    }
    __syncthreads();

    find_pivot(hist, kk, &s_pivot, &s_below, wsum);
    const int d0 = s_pivot;
    const int below0 = s_below;
    const int in0 = hist[d0];
    unsigned T;  // inclusive upper bound on sortable(x) for candidates

    if (below0 + in0 <= BUFCAP) {
        T = ((unsigned)d0 << 20) | 0xFFFFFu;
    } else {
        // ---- rare refinement level 1: bits [8,20) within pivot bin ----
        __syncthreads();
        for (int i = t; i < NBINS; i += NTHREADS) hist[i] = 0;
        __syncthreads();
        for (int i = t; i < n; i += NTHREADS) {
            float2 c = __ldg(base + i);
            unsigned u = fkey(c.x);
            if ((u >> 20) == (unsigned)d0) atomicAdd(&hist[(u >> 8) & 0xFFFu], 1);
        }
        __syncthreads();
        find_pivot(hist, kk - below0, &s_pivot, &s_below, wsum);
        const int d1 = s_pivot;
        const int below1 = s_below;
        const int in1 = hist[d1];
        if (below0 + below1 + in1 <= BUFCAP) {
            T = ((unsigned)d0 << 20) | ((unsigned)d1 << 8) | 0xFFu;
        } else {
            // ---- rare refinement level 2: low 8 bits (exact threshold) ----
            __syncthreads();
            for (int i = t; i < NBINS; i += NTHREADS) hist[i] = 0;
            __syncthreads();
            const unsigned pref = ((unsigned)d0 << 12) | (unsigned)d1;
            for (int i = t; i < n; i += NTHREADS) {
                float2 c = __ldg(base + i);
                unsigned u = fkey(c.x);
                if ((u >> 8) == pref) atomicAdd(&hist[u & 0xFFu], 1);
            }
            __syncthreads();
            find_pivot(hist, kk - below0 - below1, &s_pivot, &s_below, wsum);
            T = ((unsigned)d0 << 20) | ((unsigned)d1 << 8) | (unsigned)s_pivot;
        }
    }

    // ---- Pass 2: gather candidate 64-bit keys (x,y) ----
    if (t == 0) s_cnt = 0;
    __syncthreads();
    for (int i = t; i < n; i += NTHREADS) {
        float2 c = __ldg(base + i);
        unsigned u = fkey(c.x);
        if (u <= T) {
            int pos = atomicAdd(&s_cnt, 1);
            if (pos < BUFCAP)
                buf[pos] = ((unsigned long long)u << 32) | (unsigned long long)fkey(c.y);
        }
    }
    __syncthreads();

    int C = s_cnt < BUFCAP ? s_cnt : BUFCAP;   // C >= kk by pivot construction
    int P = 1;
    while (P < C) P <<= 1;
    for (int i = C + t; i < P; i += NTHREADS) buf[i] = 0xFFFFFFFFFFFFFFFFull;
    __syncthreads();

    // ---- bitonic sort ascending of buf[0..P) ----
    for (int size = 2; size <= P; size <<= 1) {
        for (int stride = size >> 1; stride > 0; stride >>= 1) {
            for (int i = t; i < P; i += NTHREADS) {
                int j = i ^ stride;
                if (j > i) {
                    unsigned long long a = buf[i], bb = buf[j];
                    bool up = ((i & size) == 0);
                    if ((a > bb) == up) { buf[i] = bb; buf[j] = a; }
                }
            }
            __syncthreads();
        }
    }

    // ---- emit K sorted pairs, pad with 0 ----
    float2 o = make_float2(0.f, 0.f);
    if (t < kk) {
        unsigned long long v = buf[t];
        o = make_float2(finv((unsigned)(v >> 32)), finv((unsigned)v));
    }
    outp[t] = o;
}

extern "C" void kernel_launch(void* const* d_in, const int* in_sizes, int n_in,
                              void* d_out, int out_size) {
    const float2* corners = (const float2*)d_in[0];
    const int*    lengths = (const int*)d_in[1];
    float2*       out     = (float2*)d_out;
    const int B = in_sizes[1];
    const int M = in_sizes[0] / (B * 2);
    topk_sort_kernel<<<B, NTHREADS>>>(corners, lengths, out, M);
}